// round 9
// baseline (speedup 1.0000x reference)
#include <cuda_runtime.h>
#include <cuda_fp16.h>
#include <cstdint>

// ---------------------------------------------------------------------------
// RxnPredictor: dual D-MPNN graph conv + mol pooling + reaction MLP
// R8: 3xFP16 split GEMMs; BM=64 / 256-thread CTAs with 2 CTAs per SM so
// barrier bubbles of one CTA hide under the MMA phase of the other.
// ---------------------------------------------------------------------------

#define MAXB  200000
#define HDIM  256
#define NMOLS 2048
#define NEI   10
#define WSTR  352          // padded K stride for pre-split weights (>=352)

__device__ float g_nih [MAXB * HDIM];
__device__ float g_msgA[MAXB * HDIM];
__device__ float g_msgB[MAXB * HDIM];
__device__ float g_mol [2][NMOLS * HDIM];
__device__ __half g_Wb[6 * 256 * WSTR];   // big halves, 6 matrices
__device__ __half g_Ws[6 * 256 * WSTR];   // small halves

// ---------------------------------------------------------------------------
// helpers
// ---------------------------------------------------------------------------
__device__ __forceinline__ uint32_t pack_h2(__half lo, __half hi) {
    __half2 h = __halves2half2(lo, hi);
    return *reinterpret_cast<uint32_t*>(&h);
}
__device__ __forceinline__ void split2(float x, float y, uint32_t& b, uint32_t& s) {
    __half hx = __float2half_rn(x), hy = __float2half_rn(y);
    float rx = x - __half2float(hx), ry = y - __half2float(hy);
    b = pack_h2(hx, hy);
    s = pack_h2(__float2half_rn(rx), __float2half_rn(ry));
}
__device__ __forceinline__ void mma_f16(float* d, const uint32_t* a,
                                        uint32_t b0, uint32_t b1) {
    asm volatile(
        "mma.sync.aligned.m16n8k16.row.col.f32.f16.f16.f32 "
        "{%0,%1,%2,%3}, {%4,%5,%6,%7}, {%8,%9}, {%0,%1,%2,%3};"
        : "+f"(d[0]), "+f"(d[1]), "+f"(d[2]), "+f"(d[3])
        : "r"(a[0]), "r"(a[1]), "r"(a[2]), "r"(a[3]), "r"(b0), "r"(b1));
}

// ---------------------------------------------------------------------------
// Fused weight pre-split: one launch, blockIdx.y = matrix slot (0..5).
// Slots: 0=Wi_s, 1=Wh_s, 2=Wo_s(perm), 3=Wi_t, 4=Wh_t, 5=Wo_t(perm).
// Wo permutation: [gather(256) | fatoms(82)].
// ---------------------------------------------------------------------------
__global__ void split_all_w_kernel(const float* __restrict__ Wi_s, const float* __restrict__ Wh_s,
                                   const float* __restrict__ Wo_s, const float* __restrict__ Wi_t,
                                   const float* __restrict__ Wh_t, const float* __restrict__ Wo_t,
                                   __half* __restrict__ Wb, __half* __restrict__ Ws)
{
    const int slot = blockIdx.y;
    int i = blockIdx.x * 256 + threadIdx.x;
    if (i >= 256 * WSTR) return;
    int n = i / WSTR, k = i % WSTR;
    const float* W; int Ksrc; int perm;
    switch (slot) {
        case 0: W = Wi_s; Ksrc = 88;  perm = 0; break;
        case 1: W = Wh_s; Ksrc = 256; perm = 0; break;
        case 2: W = Wo_s; Ksrc = 338; perm = 1; break;
        case 3: W = Wi_t; Ksrc = 88;  perm = 0; break;
        case 4: W = Wh_t; Ksrc = 256; perm = 0; break;
        default: W = Wo_t; Ksrc = 338; perm = 1; break;
    }
    float v = 0.f;
    if (perm) {
        if (k < 256)      v = W[n * 338 + 82 + k];
        else if (k < 338) v = W[n * 338 + (k - 256)];
    } else if (k < Ksrc) {
        v = W[n * Ksrc + k];
    }
    __half hb = __float2half_rn(v);
    size_t o = (size_t)slot * 256 * WSTR + i;
    Wb[o] = hb;
    Ws[o] = __float2half_rn(v - __half2float(hb));
}

// ---------------------------------------------------------------------------
// 3xFP16 GEMM: C[M x 256] = epilogue(A[M x K] @ W[256 x K]^T)
// Block 256 thr, BM=64, BN=256, BK=16, 2 CTAs/SM. Warp grid 2(m) x 4(n),
// warp tile 32x64 = 2 m-atoms x 8 n-atoms of m16n8k16. Passes: bb + bs + sb.
// MODE 0: A = src dense [M x Kd]; out=raw, out2=relu      (input, Kd=88)
// MODE 1: A[m,:] = sum_j src[graph[m,j],:]; out=relu(v+extra) (K=256)
// MODE 2: A = [gather(256) | fatoms(82)]; out=relu(v+bias)    (K=338)
// ---------------------------------------------------------------------------
#define BM 64
#define AROW 12
#define A_SZ (BM * AROW)
#define B_SZ (256 * AROW)
#define A_BIG(st) ((st) * A_SZ)
#define A_SML(st) (2 * A_SZ + (st) * A_SZ)
#define B_BIG(st) (4 * A_SZ + (st) * B_SZ)
#define B_SML(st) (4 * A_SZ + 2 * B_SZ + (st) * B_SZ)
#define SIDX_OFF  (4 * A_SZ + 4 * B_SZ)
#define SMEM_U32  (SIDX_OFF + BM * NEI)
#define SMEM_BYTES (SMEM_U32 * 4)

template <int MODE>
__global__ __launch_bounds__(256, 2)
void h16_gemm_kernel(const float* __restrict__ src,
                     const int*   __restrict__ graph,
                     const __half* __restrict__ Wb,
                     const __half* __restrict__ Ws,
                     const float* __restrict__ extra,  // nih (M1) / fatoms (M2)
                     const float* __restrict__ bias,   // bo (M2)
                     float* __restrict__ out,
                     float* __restrict__ out2,         // msg (M0)
                     int M, int nk, int Kd, int max_nei)
{
    extern __shared__ uint32_t SM[];
    int* sIdx = (int*)(SM + SIDX_OFF);

    const int t    = threadIdx.x;
    const int lane = t & 31;
    const int wid  = t >> 5;          // 0..7
    const int gid  = lane >> 2;
    const int tig  = lane & 3;
    const int wm0  = (wid & 1) * 32;  // 2 m-warps
    const int wn0  = (wid >> 1) * 64; // 4 n-warps
    const int m0   = blockIdx.x * BM;
    const int r    = t >> 2;          // A row (0..63)
    const int q    = t & 3;           // A k-quad (0..3)

    if (MODE != 0) {
        for (int i = t; i < BM * NEI; i += 256) {
            int rr = i / NEI, j = i % NEI;
            int m = m0 + rr;
            sIdx[i] = (m < M && j < max_nei) ? graph[m * max_nei + j] : -1;
        }
    }
    __syncthreads();

    float acc[2][8][4];
#pragma unroll
    for (int a = 0; a < 2; a++)
#pragma unroll
        for (int b = 0; b < 8; b++)
#pragma unroll
            for (int c = 0; c < 4; c++) acc[a][b][c] = 0.f;

    float4 av;                    // A prefetch (fp32, split at store)
    uint4  bvb0, bvb1, bvs0, bvs1; // B prefetch (row t, k0..k0+15)

    auto load_tile = [&](int kb) {
        const int k0 = kb * 16;
        av = make_float4(0.f, 0.f, 0.f, 0.f);
        const int m = m0 + r;
        if (m < M) {
            if (MODE == 0) {
                const int k = k0 + q * 4;
                if (k + 3 < Kd)
                    av = *(const float4*)(src + (size_t)m * Kd + k);
            } else if (MODE == 1 || (MODE == 2 && k0 < 256)) {
                const float4* bp = (const float4*)src + (k0 >> 2) + q;
                const int* ip = sIdx + r * NEI;
                float4 v0, v1, v2, v3, v4;
#pragma unroll
                for (int w = 0; w < 2; w++) {
                    int s0 = ip[w * 5 + 0], s1 = ip[w * 5 + 1], s2 = ip[w * 5 + 2];
                    int s3 = ip[w * 5 + 3], s4 = ip[w * 5 + 4];
                    v0 = (s0 >= 0) ? bp[s0 * 64] : make_float4(0, 0, 0, 0);
                    v1 = (s1 >= 0) ? bp[s1 * 64] : make_float4(0, 0, 0, 0);
                    v2 = (s2 >= 0) ? bp[s2 * 64] : make_float4(0, 0, 0, 0);
                    v3 = (s3 >= 0) ? bp[s3 * 64] : make_float4(0, 0, 0, 0);
                    v4 = (s4 >= 0) ? bp[s4 * 64] : make_float4(0, 0, 0, 0);
                    av.x += v0.x + v1.x + v2.x + v3.x + v4.x;
                    av.y += v0.y + v1.y + v2.y + v3.y + v4.y;
                    av.z += v0.z + v1.z + v2.z + v3.z + v4.z;
                    av.w += v0.w + v1.w + v2.w + v3.w + v4.w;
                }
            } else {  // MODE 2 tail: fatoms columns (k-256 < 82)
                float tmpv[4];
#pragma unroll
                for (int c = 0; c < 4; c++) {
                    int kk = k0 + q * 4 + c - 256;
                    tmpv[c] = (kk < 82) ? extra[m * 82 + kk] : 0.f;
                }
                av = make_float4(tmpv[0], tmpv[1], tmpv[2], tmpv[3]);
            }
        }
        // B: row t, full 16-k slab (2 x uint4 big + 2 x uint4 small)
        const size_t bo = (size_t)t * WSTR + k0;
        bvb0 = *(const uint4*)(Wb + bo);
        bvb1 = *(const uint4*)(Wb + bo + 8);
        bvs0 = *(const uint4*)(Ws + bo);
        bvs1 = *(const uint4*)(Ws + bo + 8);
    };

    auto store_tile = [&](int st) {
        uint32_t* Ab = SM + A_BIG(st);
        uint32_t* As = SM + A_SML(st);
        uint32_t* Bb = SM + B_BIG(st);
        uint32_t* Bs = SM + B_SML(st);
        uint32_t b0, s0, b1, s1;
        split2(av.x, av.y, b0, s0);
        split2(av.z, av.w, b1, s1);
        *(uint2*)&Ab[r * AROW + q * 2] = make_uint2(b0, b1);
        *(uint2*)&As[r * AROW + q * 2] = make_uint2(s0, s1);
        *(uint4*)&Bb[t * AROW + 0] = bvb0;
        *(uint4*)&Bb[t * AROW + 4] = bvb1;
        *(uint4*)&Bs[t * AROW + 0] = bvs0;
        *(uint4*)&Bs[t * AROW + 4] = bvs1;
    };

    load_tile(0);
    store_tile(0);
    __syncthreads();

    int cur = 0;
    for (int kb = 0; kb < nk; kb++) {
        const bool pf = (kb + 1 < nk);
        if (pf) load_tile(kb + 1);

        const uint32_t* Ab = SM + A_BIG(cur);
        const uint32_t* As = SM + A_SML(cur);
        const uint32_t* Bb = SM + B_BIG(cur);
        const uint32_t* Bs = SM + B_SML(cur);

        uint32_t afb[2][4], afs[2][4];
#pragma unroll
        for (int ma = 0; ma < 2; ma++) {
            int row = wm0 + ma * 16 + gid;
            int o0 = row * AROW + tig;
            int o1 = (row + 8) * AROW + tig;
            afb[ma][0] = Ab[o0];     afb[ma][1] = Ab[o1];
            afb[ma][2] = Ab[o0 + 4]; afb[ma][3] = Ab[o1 + 4];
            afs[ma][0] = As[o0];     afs[ma][1] = As[o1];
            afs[ma][2] = As[o0 + 4]; afs[ma][3] = As[o1 + 4];
        }
#pragma unroll
        for (int na = 0; na < 8; na++) {
            int col = wn0 + na * 8 + gid;
            int ob = col * AROW + tig;
            uint32_t bb0 = Bb[ob], bb1 = Bb[ob + 4];
            uint32_t bs0 = Bs[ob], bs1 = Bs[ob + 4];
            mma_f16(acc[0][na], afb[0], bb0, bb1);   // big*big
            mma_f16(acc[1][na], afb[1], bb0, bb1);
            mma_f16(acc[0][na], afb[0], bs0, bs1);   // big*small
            mma_f16(acc[1][na], afb[1], bs0, bs1);
            mma_f16(acc[0][na], afs[0], bb0, bb1);   // small*big
            mma_f16(acc[1][na], afs[1], bb0, bb1);
        }

        if (pf) store_tile(cur ^ 1);
        __syncthreads();
        cur ^= 1;
    }

    // ---- epilogue ----
#pragma unroll
    for (int ma = 0; ma < 2; ma++) {
        int mrow0 = m0 + wm0 + ma * 16 + gid;
#pragma unroll
        for (int na = 0; na < 8; na++) {
            int n = wn0 + na * 8 + 2 * tig;
            float v0 = acc[ma][na][0], v1 = acc[ma][na][1];
            float v2 = acc[ma][na][2], v3 = acc[ma][na][3];
#pragma unroll
            for (int h = 0; h < 2; h++) {
                int m = mrow0 + h * 8;
                if (m >= M) continue;
                float a = h ? v2 : v0, b = h ? v3 : v1;
                int o = m * HDIM + n;
                if (MODE == 0) {
                    *(float2*)(out + o)  = make_float2(a, b);
                    *(float2*)(out2 + o) = make_float2(fmaxf(a, 0.f), fmaxf(b, 0.f));
                } else if (MODE == 1) {
                    float2 e = *(const float2*)(extra + o);
                    *(float2*)(out + o) =
                        make_float2(fmaxf(a + e.x, 0.f), fmaxf(b + e.y, 0.f));
                } else {
                    *(float2*)(out + o) =
                        make_float2(fmaxf(a + bias[n], 0.f), fmaxf(b + bias[n + 1], 0.f));
                }
            }
        }
    }
}

// ---------------------------------------------------------------------------
// Segment sum over sorted mol_idx. One block per molecule, 256 threads.
// ---------------------------------------------------------------------------
__global__ void segsum_kernel(const float* __restrict__ atom_h,
                              const int* __restrict__ mol_idx,
                              float* __restrict__ mol_h, int n_atoms)
{
    const int m = blockIdx.x;
    const int t = threadIdx.x;
    int lo = 0, hi = n_atoms;
    while (lo < hi) { int mid = (lo + hi) >> 1; if (mol_idx[mid] < m) lo = mid + 1; else hi = mid; }
    int start = lo;
    hi = n_atoms;
    while (lo < hi) { int mid = (lo + hi) >> 1; if (mol_idx[mid] <= m) lo = mid + 1; else hi = mid; }
    int end = lo;
    float acc = 0.f;
    for (int a = start; a < end; a++) acc += atom_h[a * HDIM + t];
    mol_h[m * HDIM + t] = acc;
}

// ---------------------------------------------------------------------------
// Final MLP: out[m] = relu((tgt-src) @ Wrh^T + brh) @ Wro^T + bro
// ---------------------------------------------------------------------------
__global__ void rxn_kernel(const float* __restrict__ src_mol,
                           const float* __restrict__ tgt_mol,
                           const float* __restrict__ Wrh,
                           const float* __restrict__ brh,
                           const float* __restrict__ Wro,
                           const float* __restrict__ bro,
                           float* __restrict__ out)
{
    __shared__ float diff[HDIM];
    __shared__ float red[HDIM];
    const int m = blockIdx.x;
    const int t = threadIdx.x;
    diff[t] = tgt_mol[m * HDIM + t] - src_mol[m * HDIM + t];
    __syncthreads();
    float s = 0.f;
    const float* wr = Wrh + t * HDIM;
#pragma unroll 8
    for (int k = 0; k < HDIM; k++) s = fmaf(diff[k], __ldg(wr + k), s);
    s = fmaxf(s + brh[t], 0.f);
    red[t] = s * Wro[t];
    __syncthreads();
    for (int o = 128; o > 0; o >>= 1) {
        if (t < o) red[t] += red[t + o];
        __syncthreads();
    }
    if (t == 0) out[m] = red[0] + bro[0];
}

// ---------------------------------------------------------------------------
// Host launcher
// ---------------------------------------------------------------------------
extern "C" void kernel_launch(void* const* d_in, const int* in_sizes, int n_in,
                              void* d_out, int out_size)
{
    const float* fatoms[2]  = { (const float*)d_in[0], (const float*)d_in[5] };
    const float* fbonds[2]  = { (const float*)d_in[1], (const float*)d_in[6] };
    const int*   agraph[2]  = { (const int*)d_in[2],   (const int*)d_in[7] };
    const int*   bgraph[2]  = { (const int*)d_in[3],   (const int*)d_in[8] };
    const int*   mol_idx[2] = { (const int*)d_in[4],   (const int*)d_in[9] };
    const float* Wi[2] = { (const float*)d_in[10], (const float*)d_in[14] };
    const float* Wh[2] = { (const float*)d_in[11], (const float*)d_in[15] };
    const float* Wo[2] = { (const float*)d_in[12], (const float*)d_in[16] };
    const float* bo[2] = { (const float*)d_in[13], (const float*)d_in[17] };
    const float* Wrh = (const float*)d_in[18];
    const float* brh = (const float*)d_in[19];
    const float* Wro = (const float*)d_in[20];
    const float* bro = (const float*)d_in[21];

    const int n_atoms = in_sizes[0] / 82;
    const int n_bonds = in_sizes[1] / 88;
    const int max_nei = in_sizes[2] / n_atoms;

    cudaFuncSetAttribute(h16_gemm_kernel<0>,
                         cudaFuncAttributeMaxDynamicSharedMemorySize, SMEM_BYTES);
    cudaFuncSetAttribute(h16_gemm_kernel<1>,
                         cudaFuncAttributeMaxDynamicSharedMemorySize, SMEM_BYTES);
    cudaFuncSetAttribute(h16_gemm_kernel<2>,
                         cudaFuncAttributeMaxDynamicSharedMemorySize, SMEM_BYTES);

    float *nih, *msgA, *msgB, *mol;
    __half *Wbase_b, *Wbase_s;
    cudaGetSymbolAddress((void**)&nih,  g_nih);
    cudaGetSymbolAddress((void**)&msgA, g_msgA);
    cudaGetSymbolAddress((void**)&msgB, g_msgB);
    cudaGetSymbolAddress((void**)&mol,  g_mol);
    cudaGetSymbolAddress((void**)&Wbase_b, g_Wb);
    cudaGetSymbolAddress((void**)&Wbase_s, g_Ws);
    float* atom_h = nih;   // alias: nih dead after last MP GEMM epilogue read

    // one fused weight-split launch (slots 0..5)
    const int MS = 256 * WSTR;
    dim3 gSplit((256 * WSTR + 255) / 256, 6);
    split_all_w_kernel<<<gSplit, 256>>>(Wi[0], Wh[0], Wo[0], Wi[1], Wh[1], Wo[1],
                                        Wbase_b, Wbase_s);

    const int gB = (n_bonds + BM - 1) / BM;
    const int gA = (n_atoms + BM - 1) / BM;

    for (int g = 0; g < 2; g++) {
        float* mol_g = mol + g * (NMOLS * HDIM);
        const __half* Wib = Wbase_b + (3*g+0)*MS; const __half* Wis = Wbase_s + (3*g+0)*MS;
        const __half* Whb = Wbase_b + (3*g+1)*MS; const __half* Whs = Wbase_s + (3*g+1)*MS;
        const __half* Wob = Wbase_b + (3*g+2)*MS; const __half* Wos = Wbase_s + (3*g+2)*MS;

        // nih = fbonds @ Wi^T ; msgA = relu(nih)   (Kd=88, nk=6)
        h16_gemm_kernel<0><<<gB, 256, SMEM_BYTES>>>(
            fbonds[g], nullptr, Wib, Wis, nullptr, nullptr,
            nih, msgA, n_bonds, 6, 88, max_nei);

        // 3 MP iterations (K=256, nk=16), msg ping-pongs
        float* bufs[2] = { msgA, msgB };
        int cur = 0;
        for (int d = 0; d < 3; d++) {
            h16_gemm_kernel<1><<<gB, 256, SMEM_BYTES>>>(
                bufs[cur], bgraph[g], Whb, Whs, nih, nullptr,
                bufs[1 - cur], nullptr, n_bonds, 16, 256, max_nei);
            cur = 1 - cur;
        }

        // atom_h = relu([gather(256) | fatoms(82)] @ Wo'^T + bo)  (nk=22)
        h16_gemm_kernel<2><<<gA, 256, SMEM_BYTES>>>(
            bufs[cur], agraph[g], Wob, Wos, fatoms[g], bo[g],
            atom_h, nullptr, n_atoms, 22, 338, max_nei);

        segsum_kernel<<<NMOLS, 256>>>(atom_h, mol_idx[g], mol_g, n_atoms);
    }

    rxn_kernel<<<NMOLS, 256>>>(mol, mol + NMOLS * HDIM,
                               Wrh, brh, Wro, bro, (float*)d_out);
}

// round 10
// speedup vs baseline: 1.0376x; 1.0376x over previous
#include <cuda_runtime.h>
#include <cuda_fp16.h>
#include <cstdint>

// ---------------------------------------------------------------------------
// RxnPredictor: dual D-MPNN graph conv + mol pooling + reaction MLP
// R9: BM=128 (1 CTA/SM) + ldmatrix fragment loads (48 LDS -> 12 LDSM.x4
// per warp per k-block) to relieve the L1 wavefront bottleneck.
// ---------------------------------------------------------------------------

#define MAXB  200000
#define HDIM  256
#define NMOLS 2048
#define NEI   10
#define WSTR  352          // padded K stride for pre-split weights (>=352)

__device__ float g_nih [MAXB * HDIM];
__device__ float g_msgA[MAXB * HDIM];
__device__ float g_msgB[MAXB * HDIM];
__device__ float g_mol [2][NMOLS * HDIM];
__device__ __half g_Wb[6 * 256 * WSTR];   // big halves, 6 matrices
__device__ __half g_Ws[6 * 256 * WSTR];   // small halves

// ---------------------------------------------------------------------------
// helpers
// ---------------------------------------------------------------------------
__device__ __forceinline__ uint32_t pack_h2(__half lo, __half hi) {
    __half2 h = __halves2half2(lo, hi);
    return *reinterpret_cast<uint32_t*>(&h);
}
__device__ __forceinline__ void split2(float x, float y, uint32_t& b, uint32_t& s) {
    __half hx = __float2half_rn(x), hy = __float2half_rn(y);
    float rx = x - __half2float(hx), ry = y - __half2float(hy);
    b = pack_h2(hx, hy);
    s = pack_h2(__float2half_rn(rx), __float2half_rn(ry));
}
__device__ __forceinline__ void mma_f16(float* d, const uint32_t* a,
                                        uint32_t b0, uint32_t b1) {
    asm volatile(
        "mma.sync.aligned.m16n8k16.row.col.f32.f16.f16.f32 "
        "{%0,%1,%2,%3}, {%4,%5,%6,%7}, {%8,%9}, {%0,%1,%2,%3};"
        : "+f"(d[0]), "+f"(d[1]), "+f"(d[2]), "+f"(d[3])
        : "r"(a[0]), "r"(a[1]), "r"(a[2]), "r"(a[3]), "r"(b0), "r"(b1));
}
__device__ __forceinline__ void ldsm_x4(uint32_t* r, uint32_t addr) {
    asm volatile("ldmatrix.sync.aligned.m8n8.x4.shared.b16 {%0,%1,%2,%3}, [%4];"
                 : "=r"(r[0]), "=r"(r[1]), "=r"(r[2]), "=r"(r[3]) : "r"(addr));
}
__device__ __forceinline__ uint32_t smem_u32(const void* p) {
    uint32_t a;
    asm("{ .reg .u64 t; cvta.to.shared.u64 t, %1; cvt.u32.u64 %0, t; }"
        : "=r"(a) : "l"(p));
    return a;
}

// ---------------------------------------------------------------------------
// Fused weight pre-split: one launch, blockIdx.y = matrix slot (0..5).
// Slots: 0=Wi_s, 1=Wh_s, 2=Wo_s(perm), 3=Wi_t, 4=Wh_t, 5=Wo_t(perm).
// Wo permutation: [gather(256) | fatoms(82)].
// ---------------------------------------------------------------------------
__global__ void split_all_w_kernel(const float* __restrict__ Wi_s, const float* __restrict__ Wh_s,
                                   const float* __restrict__ Wo_s, const float* __restrict__ Wi_t,
                                   const float* __restrict__ Wh_t, const float* __restrict__ Wo_t,
                                   __half* __restrict__ Wb, __half* __restrict__ Ws)
{
    const int slot = blockIdx.y;
    int i = blockIdx.x * 256 + threadIdx.x;
    if (i >= 256 * WSTR) return;
    int n = i / WSTR, k = i % WSTR;
    const float* W; int Ksrc; int perm;
    switch (slot) {
        case 0: W = Wi_s; Ksrc = 88;  perm = 0; break;
        case 1: W = Wh_s; Ksrc = 256; perm = 0; break;
        case 2: W = Wo_s; Ksrc = 338; perm = 1; break;
        case 3: W = Wi_t; Ksrc = 88;  perm = 0; break;
        case 4: W = Wh_t; Ksrc = 256; perm = 0; break;
        default: W = Wo_t; Ksrc = 338; perm = 1; break;
    }
    float v = 0.f;
    if (perm) {
        if (k < 256)      v = W[n * 338 + 82 + k];
        else if (k < 338) v = W[n * 338 + (k - 256)];
    } else if (k < Ksrc) {
        v = W[n * Ksrc + k];
    }
    __half hb = __float2half_rn(v);
    size_t o = (size_t)slot * 256 * WSTR + i;
    Wb[o] = hb;
    Ws[o] = __float2half_rn(v - __half2float(hb));
}

// ---------------------------------------------------------------------------
// 3xFP16 GEMM: C[M x 256] = epilogue(A[M x K] @ W[256 x K]^T)
// Block 512 thr, BM=128, BN=256, BK=16. Warp grid 4(m) x 4(n), warp tile
// 32x64 = 2 m-atoms x 8 n-atoms of m16n8k16. Passes: bb + bs + sb.
// Fragments loaded via ldmatrix.x4 (conflict-free with 48B row stride).
// MODE 0: A = src dense [M x Kd]; out=raw, out2=relu      (input, Kd=88)
// MODE 1: A[m,:] = sum_j src[graph[m,j],:]; out=relu(v+extra) (K=256)
// MODE 2: A = [gather(256) | fatoms(82)]; out=relu(v+bias)    (K=338)
// ---------------------------------------------------------------------------
#define BM 128
#define AROW 12
#define A_SZ (BM * AROW)
#define B_SZ (256 * AROW)
#define A_BIG(st) ((st) * A_SZ)
#define A_SML(st) (2 * A_SZ + (st) * A_SZ)
#define B_BIG(st) (4 * A_SZ + (st) * B_SZ)
#define B_SML(st) (4 * A_SZ + 2 * B_SZ + (st) * B_SZ)
#define SIDX_OFF  (4 * A_SZ + 4 * B_SZ)
#define SMEM_U32  (SIDX_OFF + BM * NEI)
#define SMEM_BYTES (SMEM_U32 * 4)

template <int MODE>
__global__ __launch_bounds__(512)
void h16_gemm_kernel(const float* __restrict__ src,
                     const int*   __restrict__ graph,
                     const __half* __restrict__ Wb,
                     const __half* __restrict__ Ws,
                     const float* __restrict__ extra,  // nih (M1) / fatoms (M2)
                     const float* __restrict__ bias,   // bo (M2)
                     float* __restrict__ out,
                     float* __restrict__ out2,         // msg (M0)
                     int M, int nk, int Kd, int max_nei)
{
    extern __shared__ uint32_t SM[];
    int* sIdx = (int*)(SM + SIDX_OFF);

    const int t    = threadIdx.x;
    const int lane = t & 31;
    const int wid  = t >> 5;
    const int gid  = lane >> 2;
    const int tig  = lane & 3;
    const int wm0  = (wid & 3) * 32;  // 4 m-warps
    const int wn0  = (wid >> 2) * 64; // 4 n-warps
    const int m0   = blockIdx.x * BM;
    const int r    = t >> 2;          // A row (0..127)
    const int q    = t & 3;           // A k-quad (0..3)
    const int bnn  = t >> 1;          // B row (0..255)
    const int bpt  = t & 1;           // B half-row part

    if (MODE != 0) {
        for (int i = t; i < BM * NEI; i += 512) {
            int rr = i / NEI, j = i % NEI;
            int m = m0 + rr;
            sIdx[i] = (m < M && j < max_nei) ? graph[m * max_nei + j] : -1;
        }
    }
    __syncthreads();

    // ---- ldmatrix lane addresses (stage-0 big buffers; toggled by offset) ---
    const uint32_t smbase = smem_u32(SM);
    const int g8 = lane & 7;
    uint32_t aAddr[2];
#pragma unroll
    for (int ma = 0; ma < 2; ma++) {
        int row = wm0 + ma * 16 + g8 + ((lane >> 3) & 1) * 8;
        int byo = ((lane >> 4) & 1) * 16;
        aAddr[ma] = smbase + (uint32_t)(row * AROW) * 4u + byo;
    }
    uint32_t bAddr[4];
#pragma unroll
    for (int pa = 0; pa < 4; pa++) {
        int col = wn0 + pa * 16 + ((lane >> 4) & 1) * 8 + g8;
        int byo = ((lane >> 3) & 1) * 16;
        bAddr[pa] = smbase + (uint32_t)(B_BIG(0) + col * AROW) * 4u + byo;
    }

    float acc[2][8][4];
#pragma unroll
    for (int a = 0; a < 2; a++)
#pragma unroll
        for (int b = 0; b < 8; b++)
#pragma unroll
            for (int c = 0; c < 4; c++) acc[a][b][c] = 0.f;

    float4 av;           // A prefetch (fp32, split at store)
    uint4  bvb, bvs;     // B prefetch (pre-split halves)

    auto load_tile = [&](int kb) {
        const int k0 = kb * 16;
        av = make_float4(0.f, 0.f, 0.f, 0.f);
        const int m = m0 + r;
        if (m < M) {
            if (MODE == 0) {
                const int k = k0 + q * 4;
                if (k + 3 < Kd)
                    av = *(const float4*)(src + (size_t)m * Kd + k);
            } else if (MODE == 1 || (MODE == 2 && k0 < 256)) {
                const float4* bp = (const float4*)src + (k0 >> 2) + q;
                const int* ip = sIdx + r * NEI;
                float4 v0, v1, v2, v3, v4;
#pragma unroll
                for (int w = 0; w < 2; w++) {
                    int s0 = ip[w * 5 + 0], s1 = ip[w * 5 + 1], s2 = ip[w * 5 + 2];
                    int s3 = ip[w * 5 + 3], s4 = ip[w * 5 + 4];
                    v0 = (s0 >= 0) ? bp[s0 * 64] : make_float4(0, 0, 0, 0);
                    v1 = (s1 >= 0) ? bp[s1 * 64] : make_float4(0, 0, 0, 0);
                    v2 = (s2 >= 0) ? bp[s2 * 64] : make_float4(0, 0, 0, 0);
                    v3 = (s3 >= 0) ? bp[s3 * 64] : make_float4(0, 0, 0, 0);
                    v4 = (s4 >= 0) ? bp[s4 * 64] : make_float4(0, 0, 0, 0);
                    av.x += v0.x + v1.x + v2.x + v3.x + v4.x;
                    av.y += v0.y + v1.y + v2.y + v3.y + v4.y;
                    av.z += v0.z + v1.z + v2.z + v3.z + v4.z;
                    av.w += v0.w + v1.w + v2.w + v3.w + v4.w;
                }
            } else {  // MODE 2 tail: fatoms columns (k-256 < 82)
                float tmpv[4];
#pragma unroll
                for (int c = 0; c < 4; c++) {
                    int kk = k0 + q * 4 + c - 256;
                    tmpv[c] = (kk < 82) ? extra[m * 82 + kk] : 0.f;
                }
                av = make_float4(tmpv[0], tmpv[1], tmpv[2], tmpv[3]);
            }
        }
        // B: pre-split halves, padded stride -> unconditional LDG.128
        const size_t bo = (size_t)bnn * WSTR + k0 + bpt * 8;
        bvb = *(const uint4*)(Wb + bo);
        bvs = *(const uint4*)(Ws + bo);
    };

    auto store_tile = [&](int st) {
        uint32_t* Ab = SM + A_BIG(st);
        uint32_t* As = SM + A_SML(st);
        uint32_t* Bb = SM + B_BIG(st);
        uint32_t* Bs = SM + B_SML(st);
        uint32_t b0, s0, b1, s1;
        split2(av.x, av.y, b0, s0);
        split2(av.z, av.w, b1, s1);
        *(uint2*)&Ab[r * AROW + q * 2] = make_uint2(b0, b1);
        *(uint2*)&As[r * AROW + q * 2] = make_uint2(s0, s1);
        *(uint4*)&Bb[bnn * AROW + bpt * 4] = bvb;
        *(uint4*)&Bs[bnn * AROW + bpt * 4] = bvs;
    };

    load_tile(0);
    store_tile(0);
    __syncthreads();

    int cur = 0;
    for (int kb = 0; kb < nk; kb++) {
        const bool pf = (kb + 1 < nk);
        if (pf) load_tile(kb + 1);

        const uint32_t aoff = (uint32_t)cur * (A_SZ * 4u);
        const uint32_t boff = (uint32_t)cur * (B_SZ * 4u);

        uint32_t afb[2][4], afs[2][4];
#pragma unroll
        for (int ma = 0; ma < 2; ma++) {
            ldsm_x4(afb[ma], aAddr[ma] + aoff);
            ldsm_x4(afs[ma], aAddr[ma] + aoff + 2u * A_SZ * 4u);
        }
#pragma unroll
        for (int pa = 0; pa < 4; pa++) {
            uint32_t bb[4], bs[4];
            ldsm_x4(bb, bAddr[pa] + boff);
            ldsm_x4(bs, bAddr[pa] + boff + 2u * B_SZ * 4u);
            const int n0 = 2 * pa, n1 = 2 * pa + 1;
            mma_f16(acc[0][n0], afb[0], bb[0], bb[1]);   // big*big
            mma_f16(acc[1][n0], afb[1], bb[0], bb[1]);
            mma_f16(acc[0][n0], afb[0], bs[0], bs[1]);   // big*small
            mma_f16(acc[1][n0], afb[1], bs[0], bs[1]);
            mma_f16(acc[0][n0], afs[0], bb[0], bb[1]);   // small*big
            mma_f16(acc[1][n0], afs[1], bb[0], bb[1]);
            mma_f16(acc[0][n1], afb[0], bb[2], bb[3]);
            mma_f16(acc[1][n1], afb[1], bb[2], bb[3]);
            mma_f16(acc[0][n1], afb[0], bs[2], bs[3]);
            mma_f16(acc[1][n1], afb[1], bs[2], bs[3]);
            mma_f16(acc[0][n1], afs[0], bb[2], bb[3]);
            mma_f16(acc[1][n1], afs[1], bb[2], bb[3]);
        }

        if (pf) store_tile(cur ^ 1);
        __syncthreads();
        cur ^= 1;
    }

    // ---- epilogue ----
#pragma unroll
    for (int ma = 0; ma < 2; ma++) {
        int mrow0 = m0 + wm0 + ma * 16 + gid;
#pragma unroll
        for (int na = 0; na < 8; na++) {
            int n = wn0 + na * 8 + 2 * tig;
            float v0 = acc[ma][na][0], v1 = acc[ma][na][1];
            float v2 = acc[ma][na][2], v3 = acc[ma][na][3];
#pragma unroll
            for (int h = 0; h < 2; h++) {
                int m = mrow0 + h * 8;
                if (m >= M) continue;
                float a = h ? v2 : v0, b = h ? v3 : v1;
                int o = m * HDIM + n;
                if (MODE == 0) {
                    *(float2*)(out + o)  = make_float2(a, b);
                    *(float2*)(out2 + o) = make_float2(fmaxf(a, 0.f), fmaxf(b, 0.f));
                } else if (MODE == 1) {
                    float2 e = *(const float2*)(extra + o);
                    *(float2*)(out + o) =
                        make_float2(fmaxf(a + e.x, 0.f), fmaxf(b + e.y, 0.f));
                } else {
                    *(float2*)(out + o) =
                        make_float2(fmaxf(a + bias[n], 0.f), fmaxf(b + bias[n + 1], 0.f));
                }
            }
        }
    }
}

// ---------------------------------------------------------------------------
// Segment sum over sorted mol_idx. One block per molecule, 256 threads.
// ---------------------------------------------------------------------------
__global__ void segsum_kernel(const float* __restrict__ atom_h,
                              const int* __restrict__ mol_idx,
                              float* __restrict__ mol_h, int n_atoms)
{
    const int m = blockIdx.x;
    const int t = threadIdx.x;
    int lo = 0, hi = n_atoms;
    while (lo < hi) { int mid = (lo + hi) >> 1; if (mol_idx[mid] < m) lo = mid + 1; else hi = mid; }
    int start = lo;
    hi = n_atoms;
    while (lo < hi) { int mid = (lo + hi) >> 1; if (mol_idx[mid] <= m) lo = mid + 1; else hi = mid; }
    int end = lo;
    float acc = 0.f;
    for (int a = start; a < end; a++) acc += atom_h[a * HDIM + t];
    mol_h[m * HDIM + t] = acc;
}

// ---------------------------------------------------------------------------
// Final MLP: out[m] = relu((tgt-src) @ Wrh^T + brh) @ Wro^T + bro
// ---------------------------------------------------------------------------
__global__ void rxn_kernel(const float* __restrict__ src_mol,
                           const float* __restrict__ tgt_mol,
                           const float* __restrict__ Wrh,
                           const float* __restrict__ brh,
                           const float* __restrict__ Wro,
                           const float* __restrict__ bro,
                           float* __restrict__ out)
{
    __shared__ float diff[HDIM];
    __shared__ float red[HDIM];
    const int m = blockIdx.x;
    const int t = threadIdx.x;
    diff[t] = tgt_mol[m * HDIM + t] - src_mol[m * HDIM + t];
    __syncthreads();
    float s = 0.f;
    const float* wr = Wrh + t * HDIM;
#pragma unroll 8
    for (int k = 0; k < HDIM; k++) s = fmaf(diff[k], __ldg(wr + k), s);
    s = fmaxf(s + brh[t], 0.f);
    red[t] = s * Wro[t];
    __syncthreads();
    for (int o = 128; o > 0; o >>= 1) {
        if (t < o) red[t] += red[t + o];
        __syncthreads();
    }
    if (t == 0) out[m] = red[0] + bro[0];
}

// ---------------------------------------------------------------------------
// Host launcher
// ---------------------------------------------------------------------------
extern "C" void kernel_launch(void* const* d_in, const int* in_sizes, int n_in,
                              void* d_out, int out_size)
{
    const float* fatoms[2]  = { (const float*)d_in[0], (const float*)d_in[5] };
    const float* fbonds[2]  = { (const float*)d_in[1], (const float*)d_in[6] };
    const int*   agraph[2]  = { (const int*)d_in[2],   (const int*)d_in[7] };
    const int*   bgraph[2]  = { (const int*)d_in[3],   (const int*)d_in[8] };
    const int*   mol_idx[2] = { (const int*)d_in[4],   (const int*)d_in[9] };
    const float* Wi[2] = { (const float*)d_in[10], (const float*)d_in[14] };
    const float* Wh[2] = { (const float*)d_in[11], (const float*)d_in[15] };
    const float* Wo[2] = { (const float*)d_in[12], (const float*)d_in[16] };
    const float* bo[2] = { (const float*)d_in[13], (const float*)d_in[17] };
    const float* Wrh = (const float*)d_in[18];
    const float* brh = (const float*)d_in[19];
    const float* Wro = (const float*)d_in[20];
    const float* bro = (const float*)d_in[21];

    const int n_atoms = in_sizes[0] / 82;
    const int n_bonds = in_sizes[1] / 88;
    const int max_nei = in_sizes[2] / n_atoms;

    cudaFuncSetAttribute(h16_gemm_kernel<0>,
                         cudaFuncAttributeMaxDynamicSharedMemorySize, SMEM_BYTES);
    cudaFuncSetAttribute(h16_gemm_kernel<1>,
                         cudaFuncAttributeMaxDynamicSharedMemorySize, SMEM_BYTES);
    cudaFuncSetAttribute(h16_gemm_kernel<2>,
                         cudaFuncAttributeMaxDynamicSharedMemorySize, SMEM_BYTES);

    float *nih, *msgA, *msgB, *mol;
    __half *Wbase_b, *Wbase_s;
    cudaGetSymbolAddress((void**)&nih,  g_nih);
    cudaGetSymbolAddress((void**)&msgA, g_msgA);
    cudaGetSymbolAddress((void**)&msgB, g_msgB);
    cudaGetSymbolAddress((void**)&mol,  g_mol);
    cudaGetSymbolAddress((void**)&Wbase_b, g_Wb);
    cudaGetSymbolAddress((void**)&Wbase_s, g_Ws);
    float* atom_h = nih;   // alias: nih dead after last MP GEMM epilogue read

    // one fused weight-split launch (slots 0..5)
    const int MS = 256 * WSTR;
    dim3 gSplit((256 * WSTR + 255) / 256, 6);
    split_all_w_kernel<<<gSplit, 256>>>(Wi[0], Wh[0], Wo[0], Wi[1], Wh[1], Wo[1],
                                        Wbase_b, Wbase_s);

    const int gB = (n_bonds + BM - 1) / BM;
    const int gA = (n_atoms + BM - 1) / BM;

    for (int g = 0; g < 2; g++) {
        float* mol_g = mol + g * (NMOLS * HDIM);
        const __half* Wib = Wbase_b + (3*g+0)*MS; const __half* Wis = Wbase_s + (3*g+0)*MS;
        const __half* Whb = Wbase_b + (3*g+1)*MS; const __half* Whs = Wbase_s + (3*g+1)*MS;
        const __half* Wob = Wbase_b + (3*g+2)*MS; const __half* Wos = Wbase_s + (3*g+2)*MS;

        // nih = fbonds @ Wi^T ; msgA = relu(nih)   (Kd=88, nk=6)
        h16_gemm_kernel<0><<<gB, 512, SMEM_BYTES>>>(
            fbonds[g], nullptr, Wib, Wis, nullptr, nullptr,
            nih, msgA, n_bonds, 6, 88, max_nei);

        // 3 MP iterations (K=256, nk=16), msg ping-pongs
        float* bufs[2] = { msgA, msgB };
        int cur = 0;
        for (int d = 0; d < 3; d++) {
            h16_gemm_kernel<1><<<gB, 512, SMEM_BYTES>>>(
                bufs[cur], bgraph[g], Whb, Whs, nih, nullptr,
                bufs[1 - cur], nullptr, n_bonds, 16, 256, max_nei);
            cur = 1 - cur;
        }

        // atom_h = relu([gather(256) | fatoms(82)] @ Wo'^T + bo)  (nk=22)
        h16_gemm_kernel<2><<<gA, 512, SMEM_BYTES>>>(
            bufs[cur], agraph[g], Wob, Wos, fatoms[g], bo[g],
            atom_h, nullptr, n_atoms, 22, 338, max_nei);

        segsum_kernel<<<NMOLS, 256>>>(atom_h, mol_idx[g], mol_g, n_atoms);
    }

    rxn_kernel<<<NMOLS, 256>>>(mol, mol + NMOLS * HDIM,
                               Wrh, brh, Wro, bro, (float*)d_out);
}